// round 1
// baseline (speedup 1.0000x reference)
#include <cuda_runtime.h>
#include <cuda_bf16.h>

// FeaturesLinear: out[seg] = sum_t (weight[ids[t]] * ratings[t]) + bias
// ids:      int32  [N]         (N = 819200)
// ratings:  f32    [N]
// segs:     int32  [N]  sorted ascending
// batch:    int32  [1]  (unused; batch = out_size / 16)
// weight:   f32    [VOCAB, 16]
// bias:     f32    [16]
// out:      f32    [batch, 16]

#define DIM 16

__global__ void fl_init_out(float* __restrict__ out,
                            const float* __restrict__ bias,
                            int out_size) {
    int i = blockIdx.x * blockDim.x + threadIdx.x;
    if (i < out_size) out[i] = __ldg(&bias[i & (DIM - 1)]);
}

// 4 lanes per token (each lane owns one float4 of the 16-float row).
// 8 tokens per warp. Warp-level segmented reduction over the (sorted)
// segment ids collapses up to 8 tokens into one set of atomics.
__global__ __launch_bounds__(256)
void fl_main(const int*   __restrict__ ids,
             const float* __restrict__ ratings,
             const int*   __restrict__ segs,
             const float* __restrict__ weight,
             float*       __restrict__ out,
             int n) {
    const int lane      = threadIdx.x & 31;
    const int slot      = lane & 3;        // which float4 of the row
    const int tokInWarp = lane >> 2;       // 0..7
    const int warpsPerBlock = blockDim.x >> 5;
    const int warpId = blockIdx.x * warpsPerBlock + (threadIdx.x >> 5);

    const int t = warpId * 8 + tokInWarp;

    float4 v = make_float4(0.f, 0.f, 0.f, 0.f);
    int seg = -1;
    if (t < n) {
        const int   id = __ldg(&ids[t]);
        const float r  = __ldg(&ratings[t]);
        seg            = __ldg(&segs[t]);
        const float4 w = __ldg(&reinterpret_cast<const float4*>(weight)[(size_t)id * 4 + slot]);
        v.x = w.x * r; v.y = w.y * r; v.z = w.z * r; v.w = w.w * r;
    }

    // Segmented suffix-sum across tokens within the warp (token stride = 4 lanes).
    #pragma unroll
    for (int off = 4; off <= 16; off <<= 1) {
        int   oseg = __shfl_down_sync(0xffffffffu, seg, off);
        float ox   = __shfl_down_sync(0xffffffffu, v.x, off);
        float oy   = __shfl_down_sync(0xffffffffu, v.y, off);
        float oz   = __shfl_down_sync(0xffffffffu, v.z, off);
        float ow   = __shfl_down_sync(0xffffffffu, v.w, off);
        if ((lane + off) < 32 && oseg == seg) {
            v.x += ox; v.y += oy; v.z += oz; v.w += ow;
        }
    }

    // Run head: first token of its segment-run within this warp.
    const int pseg = __shfl_up_sync(0xffffffffu, seg, 4);
    const bool head = (tokInWarp == 0) || (pseg != seg);

    if (head && seg >= 0) {
        float* o = out + (size_t)seg * DIM + slot * 4;
        atomicAdd(o + 0, v.x);
        atomicAdd(o + 1, v.y);
        atomicAdd(o + 2, v.z);
        atomicAdd(o + 3, v.w);
    }
}

extern "C" void kernel_launch(void* const* d_in, const int* in_sizes, int n_in,
                              void* d_out, int out_size) {
    const int*   ids     = (const int*)  d_in[0];
    const float* ratings = (const float*)d_in[1];
    const int*   segs    = (const int*)  d_in[2];
    // d_in[3] = batch_size scalar (unused; derived from out_size)
    const float* weight  = (const float*)d_in[4];
    const float* bias    = (const float*)d_in[5];
    float*       out     = (float*)d_out;

    const int n = in_sizes[0];

    // Init output with bias (output buffer is poisoned by the harness).
    {
        int threads = 256;
        int blocks  = (out_size + threads - 1) / threads;
        fl_init_out<<<blocks, threads>>>(out, bias, out_size);
    }

    // Main gather + segmented reduce. 8 tokens per warp, 8 warps per block.
    {
        int warps   = (n + 7) / 8;
        int threads = 256;
        int blocks  = (warps + 7) / 8;
        fl_main<<<blocks, threads>>>(ids, ratings, segs, weight, out, n);
    }
}

// round 2
// speedup vs baseline: 1.6044x; 1.6044x over previous
#include <cuda_runtime.h>
#include <cuda_bf16.h>

// FeaturesLinear: out[seg] = sum_t (weight[ids[t]] * ratings[t]) + bias
// ids: int32[N], ratings: f32[N], segs: int32[N] (sorted), weight: f32[V,16],
// bias: f32[16], out: f32[batch,16].  N = 819200 (multiple of 32).

#define DIM 16
#define T_PER_THREAD 4   // tokens per thread

__global__ void fl_init_out(float4* __restrict__ out,
                            const float4* __restrict__ bias4,
                            int out_quads) {
    int i = blockIdx.x * blockDim.x + threadIdx.x;
    if (i < out_quads) out[i] = __ldg(&bias4[i & 3]);
}

// Lane layout: slot = lane & 3 (which float4 of the 16-float row),
// tokGroup = lane >> 2 (0..7). Thread handles T_PER_THREAD consecutive
// tokens; a warp covers 8 * T_PER_THREAD = 32 consecutive tokens.
__global__ __launch_bounds__(256)
void fl_main(const int*   __restrict__ ids,
             const float* __restrict__ ratings,
             const int*   __restrict__ segs,
             const float4* __restrict__ weight4,
             float*       __restrict__ out,
             int n) {
    const int lane     = threadIdx.x & 31;
    const int slot     = lane & 3;
    const int tokGroup = lane >> 2;
    const int warpsPerBlock = blockDim.x >> 5;
    const int warpId   = blockIdx.x * warpsPerBlock + (threadIdx.x >> 5);

    const int base = warpId * 32 + tokGroup * T_PER_THREAD;
    if (base >= n) return;

    // ---- load metadata for 4 tokens (vectorized, broadcast across 4 slots)
    int4   idv = __ldg((const int4*)  (ids     + base));
    float4 rv  = __ldg((const float4*)(ratings + base));
    int4   sv  = __ldg((const int4*)  (segs    + base));

    const int   id[4] = {idv.x, idv.y, idv.z, idv.w};
    const float r [4] = {rv.x,  rv.y,  rv.z,  rv.w};
    const int   sg[4] = {sv.x,  sv.y,  sv.z,  sv.w};

    // ---- issue all 4 independent row gathers up front (MLP = 4)
    float4 w[4];
    #pragma unroll
    for (int k = 0; k < T_PER_THREAD; k++)
        w[k] = __ldg(&weight4[(size_t)id[k] * 4 + slot]);

    // ---- thread-serial accumulation with flush on segment boundary
    float4 acc;
    acc.x = w[0].x * r[0]; acc.y = w[0].y * r[0];
    acc.z = w[0].z * r[0]; acc.w = w[0].w * r[0];

    #pragma unroll
    for (int k = 1; k < T_PER_THREAD; k++) {
        if (sg[k] != sg[k - 1]) {
            float* o = out + (size_t)sg[k - 1] * DIM + slot * 4;
            atomicAdd(o + 0, acc.x);
            atomicAdd(o + 1, acc.y);
            atomicAdd(o + 2, acc.z);
            atomicAdd(o + 3, acc.w);
            acc.x = acc.y = acc.z = acc.w = 0.f;
        }
        acc.x += w[k].x * r[k]; acc.y += w[k].y * r[k];
        acc.z += w[k].z * r[k]; acc.w += w[k].w * r[k];
    }

    // ---- cross-lane segmented suffix reduction on trailing partials.
    // Keys (trailing segment ids) are monotone across the warp, so the
    // strided conditional add is an exact segmented reduction.
    int seg = sg[T_PER_THREAD - 1];
    #pragma unroll
    for (int off = 4; off <= 16; off <<= 1) {
        int   oseg = __shfl_down_sync(0xffffffffu, seg, off);
        float ox   = __shfl_down_sync(0xffffffffu, acc.x, off);
        float oy   = __shfl_down_sync(0xffffffffu, acc.y, off);
        float oz   = __shfl_down_sync(0xffffffffu, acc.z, off);
        float ow   = __shfl_down_sync(0xffffffffu, acc.w, off);
        if ((lane + off) < 32 && oseg == seg) {
            acc.x += ox; acc.y += oy; acc.z += oz; acc.w += ow;
        }
    }

    // Head of a trailing-run within the warp flushes. A thread whose own
    // tokens ended a previous segment internally already flushed it above,
    // and its trailing key differs from the previous thread's => it is a head.
    const int  pseg = __shfl_up_sync(0xffffffffu, seg, 4);
    const bool head = (tokGroup == 0) || (pseg != seg);

    if (head) {
        float* o = out + (size_t)seg * DIM + slot * 4;
        atomicAdd(o + 0, acc.x);
        atomicAdd(o + 1, acc.y);
        atomicAdd(o + 2, acc.z);
        atomicAdd(o + 3, acc.w);
    }
}

extern "C" void kernel_launch(void* const* d_in, const int* in_sizes, int n_in,
                              void* d_out, int out_size) {
    const int*   ids     = (const int*)  d_in[0];
    const float* ratings = (const float*)d_in[1];
    const int*   segs    = (const int*)  d_in[2];
    // d_in[3] = batch_size scalar (unused)
    const float* weight  = (const float*)d_in[4];
    const float* bias    = (const float*)d_in[5];
    float*       out     = (float*)d_out;

    const int n = in_sizes[0];

    // Init output with bias (vectorized).
    {
        int quads   = out_size / 4;
        int threads = 256;
        int blocks  = (quads + threads - 1) / threads;
        fl_init_out<<<blocks, threads>>>((float4*)out, (const float4*)bias, quads);
    }

    // Main gather + segmented reduce: 32 tokens per warp, 8 warps per block.
    {
        int warps   = (n + 31) / 32;
        int threads = 256;
        int blocks  = (warps + 7) / 8;
        fl_main<<<blocks, threads>>>(ids, ratings, segs,
                                     (const float4*)weight, out, n);
    }
}